// round 11
// baseline (speedup 1.0000x reference)
#include <cuda_runtime.h>
#include <cstdint>

// GTConvAE — fully layer-fused persistent kernel, R11.
// Per layer, block (nb, tg) owns nodes n-band = nb*16..+15 and a tau-group tg.
// It computes C_b[j][n] = Sg^b[n,:] . act[j,:] for the act rows j in its window
// (B streamed through smem in 16-row chunks), then u[i][k][n] = sum_{a,b}
// c_k[a,b] v_b[tau-a] and acc[o] = sum_{i,k} h[o,i,k] u[i][k] — all block-local.
// No G1/G2 globals, 4 grid barriers total.

#define NN  192
#define TT  32
#define NB  96
#define RS  196           // smem row stride (floats)

// smem offsets (floats)
#define oA1 0             // Sg rows of band   (16 x RS)
#define oA2 3136          // Sg2 rows of band  (16 x RS)
#define oB  6272          // B chunk / scratch (16 x RS = 3136)
#define oU  6272          // u table  (<=1536) — oB reused after C-phase
#define oH  7808          // h table  (<=1536)
#define oC  9408          // C[b][64][16] = 2048
#define oCK 11456         // c_k[a][b] table (27)
#define SMF 11488         // 45.95 KB

// ---------------- scratch --------------------------------------------------------
__device__ float g_Sg2 [NN * NN];
__device__ float g_P   [TT * NN];    // P[tau][n] = (Sg @ X)[n, tau]
__device__ float g_actA[256 * NN];   // e1 out (16t x 16c), later d1 out (16t x 16c)
__device__ float g_actB[256 * NN];   // e2 out (8t x 32c)
__device__ unsigned g_flags[NB * 32];
__device__ unsigned g_gen = 0;

// ---------------- grid barrier (flag array, replay-safe) -------------------------
__device__ __forceinline__ void grid_barrier(unsigned gen)
{
    __syncthreads();
    if (blockIdx.x == 0) {
        if (threadIdx.x < NB) {
            if (threadIdx.x == 0)
                asm volatile("st.release.gpu.u32 [%0], %1;"
                             :: "l"(&g_flags[0]), "r"(gen) : "memory");
            const unsigned* fp = &g_flags[threadIdx.x * 32];
            unsigned v;
            do {
                asm volatile("ld.acquire.gpu.u32 %0, [%1];"
                             : "=r"(v) : "l"(fp) : "memory");
            } while ((int)(v - gen) < 0);
        }
        __syncthreads();
        if (threadIdx.x == 0)
            asm volatile("st.release.gpu.u32 [%0], %1;"
                         :: "l"(&g_gen), "r"(gen) : "memory");
    } else {
        if (threadIdx.x == 0) {
            asm volatile("st.release.gpu.u32 [%0], %1;"
                         :: "l"(&g_flags[blockIdx.x * 32]), "r"(gen) : "memory");
            unsigned v;
            do {
                asm volatile("ld.acquire.gpu.u32 %0, [%1];"
                             : "=r"(v) : "l"(&g_gen) : "memory");
            } while ((int)(v - gen) < 0);
        }
        __syncthreads();
    }
}

// ---------------- cp.async -------------------------------------------------------
__device__ __forceinline__ void cp16(float* dst, const float* src, bool cg)
{
    uint32_t d = (uint32_t)__cvta_generic_to_shared(dst);
    if (cg)
        asm volatile("cp.async.cg.shared.global [%0], [%1], 16;" :: "r"(d), "l"(src));
    else
        asm volatile("cp.async.ca.shared.global [%0], [%1], 16;" :: "r"(d), "l"(src));
}
__device__ __forceinline__ void cp_wait_all()
{
    asm volatile("cp.async.wait_all;" ::: "memory");
}

// 16 contiguous rows (192 floats each) -> smem at stride RS. 768 float4 ops.
__device__ __forceinline__ void load16rows(float* dst, const float* src, bool cg)
{
    #pragma unroll
    for (int r = 0; r < 3; r++) {
        int op = threadIdx.x + 256 * r;
        int ml = op / 48, kq = op - ml * 48;
        cp16(&dst[ml * RS + 4 * kq], &src[ml * 192 + 4 * kq], cg);
    }
}

__device__ __forceinline__ float dot192(const float* a, const float* b)
{
    float acc = 0.f;
    #pragma unroll 12
    for (int k = 0; k < 192; k += 4) {
        float4 x = *(const float4*)(a + k);
        float4 y = *(const float4*)(b + k);
        acc += x.x * y.x; acc += x.y * y.y; acc += x.z * y.z; acc += x.w * y.w;
    }
    return acc;
}
__device__ __forceinline__ void dot2_192(const float* a1, const float* a2,
                                         const float* b, float& r1, float& r2)
{
    float s1 = 0.f, s2 = 0.f;
    #pragma unroll 8
    for (int k = 0; k < 192; k += 4) {
        float4 y  = *(const float4*)(b + k);
        float4 x1 = *(const float4*)(a1 + k);
        float4 x2 = *(const float4*)(a2 + k);
        s1 += x1.x * y.x; s1 += x1.y * y.y; s1 += x1.z * y.z; s1 += x1.w * y.w;
        s2 += x2.x * y.x; s2 += x2.y * y.y; s2 += x2.z * y.z; s2 += x2.w * y.w;
    }
    r1 = s1; r2 = s2;
}

// u[k] = sum_{a,b} ck[k][a][b] * v[b][a]
__device__ __forceinline__ void build_u(const float* ck, const float v0[3],
                                        const float v1[3], const float v2[3],
                                        float u[3])
{
    #pragma unroll
    for (int k = 0; k < 3; k++) {
        float acc = 0.f;
        #pragma unroll
        for (int a = 0; a < 3; a++) {
            acc += ck[k * 9 + a * 3 + 0] * v0[a];
            acc += ck[k * 9 + a * 3 + 1] * v1[a];
            acc += ck[k * 9 + a * 3 + 2] * v2[a];
        }
        u[k] = acc;
    }
}

// ---------------- persistent mega-kernel ----------------------------------------
__global__ __launch_bounds__(256, 1) void mega(
    const float* __restrict__ X,    const float* __restrict__ Sg,
    const float* __restrict__ s,    const float* __restrict__ h_e1,
    const float* __restrict__ h_e2, const float* __restrict__ h_d1,
    const float* __restrict__ h_d2, float* __restrict__ out)
{
    __shared__ float sm[SMF];

    const int bid = blockIdx.x;
    const int tid = threadIdx.x;
    const int n   = tid & 15;           // node within band
    const int og  = tid >> 4;           // 0..15
    const int nb  = bid / 8;            // 12 n-bands of 16
    const int tg  = bid % 8;            // tau-group
    const int band = nb * 16;
    const int n_g  = band + n;

    unsigned basegen;
    asm volatile("ld.relaxed.gpu.u32 %0, [%1];" : "=r"(basegen) : "l"(&g_gen));

    // ================= S0: Sg2 tiles + P = Sg@X =================
    load16rows(sm + oA1, &Sg[band * 192], false);     // persistent Sg band
    if (tid < 27) {                                    // c_k[a][b] table
        int k = tid / 9, a = (tid % 9) / 3, b = tid % 3;
        float s00 = s[0], s01 = s[1], s10 = s[2], s11 = s[3];
        float sv[4] = { s00, s01, s10, s11 };
        float val;
        if (k == 0) val = (a == 0 && b == 0) ? 1.f : 0.f;
        else if (k == 1) val = (a < 2 && b < 2) ? sv[a * 2 + b] : 0.f;
        else {
            float c2 = 0.f;
            #pragma unroll
            for (int a1 = 0; a1 < 2; a1++)
                #pragma unroll
                for (int b1 = 0; b1 < 2; b1++) {
                    int a2 = a - a1, b2 = b - b1;
                    if (a2 >= 0 && a2 < 2 && b2 >= 0 && b2 < 2)
                        c2 += sv[a1 * 2 + b1] * sv[a2 * 2 + b2];
                }
            val = c2;
        }
        sm[oCK + tid] = val;
    }
    // Sg2 columns tg*24 .. +23, two passes of 12
    #pragma unroll
    for (int pass = 0; pass < 2; pass++) {
        for (int idx = tid; idx < 12 * 192; idx += 256) {
            int j = idx / 192, k = idx - j * 192;
            sm[oB + j * RS + k] = Sg[k * 192 + tg * 24 + pass * 12 + j];
        }
        if (pass == 0) cp_wait_all();
        __syncthreads();
        if (og < 12) {
            float v = dot192(sm + oA1 + n * RS, sm + oB + og * RS);
            g_Sg2[n_g * 192 + tg * 24 + pass * 12 + og] = v;
        }
        __syncthreads();
    }
    // P rows (blocks tg<2): P[tau][n] = Sg[n,:] . X[:,tau]
    if (tg < 2) {
        for (int idx = tid; idx < 16 * 192; idx += 256) {
            int t = idx / 192, k = idx - t * 192;
            sm[oB + t * RS + k] = X[k * TT + tg * 16 + t];
        }
        __syncthreads();
        float v = dot192(sm + oA1 + n * RS, sm + oB + og * RS);
        g_P[(tg * 16 + og) * 192 + n_g] = v;
    }
    grid_barrier(basegen + 1);

    // ================= S1: e1 fused (CI=1, CO=16, pool to t=16) =================
    {
        // prefetch Sg2 band for F2 (ready after barrier 1)
        load16rows(sm + oA2, &g_Sg2[band * 192], true);
        // B: 6 X-columns (strided) + 6 P-rows (cp) ; window srcs 4tg-2..4tg+3
        for (int idx = tid; idx < 6 * 192; idx += 256) {
            int w = idx / 192, k = idx - w * 192;
            int src = (4 * tg - 2 + w + TT) & (TT - 1);
            sm[oB + w * RS + k] = X[k * TT + src];
        }
        #pragma unroll
        for (int r = 0; r < 2; r++) {
            int op = tid + 256 * r;
            if (op < 288) {
                int w = op / 48, kq = op - w * 48;
                int src = (4 * tg - 2 + w + TT) & (TT - 1);
                cp16(&sm[oB + (8 + w) * RS + 4 * kq], &g_P[src * 192 + 4 * kq], true);
            }
        }
        cp_wait_all();
        __syncthreads();
        // C dots: mat 0: Sg.Xcol ; mat 1: Sg.Prow (= Sg2.Xcol)
        if (og < 12) {
            int mat = og / 6, w = og - mat * 6;
            float v = dot192(sm + oA1 + n * RS, sm + oB + (mat * 8 + w) * RS);
            sm[oC + (mat * 8 + w) * 16 + n] = v;
        }
        __syncthreads();   // oB free below EXCEPT: A2 cp already waited ✓
        // h_e1 (48) -> oH
        if (tid < 48) sm[oH + tid] = h_e1[tid];
        // u-build: og<4 -> slot tau = 4tg+og
        if (og < 4) {
            float v0[3], v1[3], v2[3], u[3];
            #pragma unroll
            for (int a = 0; a < 3; a++) {
                int src = (4 * tg + og - a + TT) & (TT - 1);
                int w = og + 2 - a;
                v0[a] = X[n_g * TT + src];
                v1[a] = sm[oC + (0 * 8 + w) * 16 + n];
                v2[a] = sm[oC + (1 * 8 + w) * 16 + n];
            }
            build_u(sm + oCK, v0, v1, v2, u);
            #pragma unroll
            for (int k = 0; k < 3; k++)
                sm[oU + 256 + (og * 3 + k) * 16 + n] = u[k];   // +256: clear of oH? no—
        }
        __syncthreads();
        // apply: o = og; 4 slots; pool pairs
        {
            float acc[4];
            #pragma unroll
            for (int sl = 0; sl < 4; sl++) {
                float a0 = 0.f;
                #pragma unroll
                for (int k = 0; k < 3; k++)
                    a0 += sm[oH + og * 3 + k] * sm[oU + 256 + (sl * 3 + k) * 16 + n];
                acc[sl] = a0;
            }
            float p0 = fmaxf(fmaxf(acc[0], acc[1]), 0.f);
            float p1 = fmaxf(fmaxf(acc[2], acc[3]), 0.f);
            g_actA[((2 * tg + 0) * 16 + og) * 192 + n_g] = p0;
            g_actA[((2 * tg + 1) * 16 + og) * 192 + n_g] = p1;
        }
    }
    grid_barrier(basegen + 2);

    // ================= F2: e2 fused (t=16, CI=16, CO=32, pool -> tp=tg) =========
    {
        // C-phase: 4 chunks, window srcs (2tg-2+c) mod 16
        #pragma unroll
        for (int c = 0; c < 4; c++) {
            int rb = ((2 * tg - 2 + c + 16) & 15) * 16;
            load16rows(sm + oB, &g_actA[rb * 192], true);
            cp_wait_all();
            __syncthreads();
            float c1, c2;
            dot2_192(sm + oA1 + n * RS, sm + oA2 + n * RS, sm + oB + og * RS, c1, c2);
            __syncthreads();          // chunk fully consumed before reload
            sm[oC + (0 * 64 + c * 16 + og) * 16 + n] = c1;
            sm[oC + (1 * 64 + c * 16 + og) * 16 + n] = c2;
        }
        __syncthreads();
        for (int idx = tid; idx < 1536; idx += 256)   // h_e2 -> oH
            sm[oH + idx] = h_e2[idx];
        float accs[2][2];
        #pragma unroll
        for (int sl = 0; sl < 2; sl++) {
            __syncthreads();
            {   // u-build: i = og
                float v0[3], v1[3], v2[3], u[3];
                #pragma unroll
                for (int a = 0; a < 3; a++) {
                    int src = (2 * tg + sl - a + 16) & 15;
                    int w = sl + 2 - a;
                    int jw = w * 16 + og;
                    v0[a] = __ldcg(&g_actA[(src * 16 + og) * 192 + n_g]);
                    v1[a] = sm[oC + (0 * 64 + jw) * 16 + n];
                    v2[a] = sm[oC + (1 * 64 + jw) * 16 + n];
                }
                build_u(sm + oCK, v0, v1, v2, u);
                #pragma unroll
                for (int k = 0; k < 3; k++)
                    sm[oU + (og * 3 + k) * 16 + n] = u[k];
            }
            __syncthreads();
            #pragma unroll
            for (int oh = 0; oh < 2; oh++) {
                int o = og + oh * 16;
                float a0 = 0.f;
                #pragma unroll
                for (int i = 0; i < 16; i++)
                    #pragma unroll
                    for (int k = 0; k < 3; k++)
                        a0 += sm[oH + (o * 16 + i) * 3 + k]
                            * sm[oU + (i * 3 + k) * 16 + n];
                accs[sl][oh] = a0;
            }
        }
        #pragma unroll
        for (int oh = 0; oh < 2; oh++) {
            int o = og + oh * 16;
            g_actB[(tg * 32 + o) * 192 + n_g] =
                fmaxf(fmaxf(accs[0][oh], accs[1][oh]), 0.f);
        }
    }
    grid_barrier(basegen + 3);

    // ================= F3: d1 fused (t=16 out, CI=32 at half-res, CO=16, relu) ==
    {
        // C-phase: 4 chunks; window tls {tg-1, tg} mod 8, 32 i each
        #pragma unroll
        for (int c = 0; c < 4; c++) {
            int tl = (tg - 1 + (c >> 1) + 8) & 7;
            int rb = tl * 32 + (c & 1) * 16;
            load16rows(sm + oB, &g_actB[rb * 192], true);
            cp_wait_all();
            __syncthreads();
            float c1, c2;
            dot2_192(sm + oA1 + n * RS, sm + oA2 + n * RS, sm + oB + og * RS, c1, c2);
            __syncthreads();
            sm[oC + (0 * 64 + c * 16 + og) * 16 + n] = c1;
            sm[oC + (1 * 64 + c * 16 + og) * 16 + n] = c2;
        }
        __syncthreads();
        for (int idx = tid; idx < 1536; idx += 256)   // h_d1 -> oH
            sm[oH + idx] = h_d1[idx];
        #pragma unroll
        for (int sl = 0; sl < 2; sl++) {             // slot tau = 2tg + sl
            __syncthreads();
            #pragma unroll
            for (int ih = 0; ih < 2; ih++) {          // i = og, og+16
                int i = og + ih * 16;
                float v0[3] = {0.f, 0.f, 0.f};
                float v1[3] = {0.f, 0.f, 0.f};
                float v2[3] = {0.f, 0.f, 0.f};
                #pragma unroll
                for (int a = 0; a < 3; a++) {
                    if (((sl - a) & 1) == 0) {        // even source only
                        int delta = (sl - a) / 2;     // 0 or -1
                        int tlg = (tg + delta + 8) & 7;
                        int w = 1 + delta;            // 0 or 1
                        int jw = w * 32 + i;          // hmm: jw mapping below
                        // C was stored chunk-major: chunk c = (w<<1)|(i>=16)
                        int cc = (w << 1) | ih;
                        int jj = cc * 16 + (i & 15);
                        v0[a] = __ldcg(&g_actB[(tlg * 32 + i) * 192 + n_g]);
                        v1[a] = sm[oC + (0 * 64 + jj) * 16 + n];
                        v2[a] = sm[oC + (1 * 64 + jj) * 16 + n];
                        (void)jw;
                    }
                }
                float u[3];
                build_u(sm + oCK, v0, v1, v2, u);
                #pragma unroll
                for (int k = 0; k < 3; k++)
                    sm[oU + (i * 3 + k) * 16 + n] = u[k];
            }
            __syncthreads();
            {   // apply: o = og
                float a0 = 0.f;
                #pragma unroll
                for (int i = 0; i < 32; i++)
                    #pragma unroll
                    for (int k = 0; k < 3; k++)
                        a0 += sm[oH + (og * 32 + i) * 3 + k]
                            * sm[oU + (i * 3 + k) * 16 + n];
                g_actA[((2 * tg + sl) * 16 + og) * 192 + n_g] = fmaxf(a0, 0.f);
            }
        }
    }
    grid_barrier(basegen + 4);

    // ================= F4: d2 fused (t=32 out, CI=16 half-res, CO=1) ============
    {
        // C-phase: 3 chunks; window tls {2tg-1, 2tg, 2tg+1} mod 16
        #pragma unroll
        for (int c = 0; c < 3; c++) {
            int tl = (2 * tg - 1 + c + 16) & 15;
            load16rows(sm + oB, &g_actA[tl * 16 * 192], true);
            cp_wait_all();
            __syncthreads();
            float c1, c2;
            dot2_192(sm + oA1 + n * RS, sm + oA2 + n * RS, sm + oB + og * RS, c1, c2);
            __syncthreads();
            sm[oC + (0 * 64 + c * 16 + og) * 16 + n] = c1;
            sm[oC + (1 * 64 + c * 16 + og) * 16 + n] = c2;
        }
        __syncthreads();
        if (tid < 48) sm[oH + tid] = h_d2[tid];       // h_d2 (1,16,3)
        // slot-sequential: 4 slots tau = 4tg + sl, oU per slot = 16i x 3k x 16n
        #pragma unroll
        for (int sl = 0; sl < 4; sl++) {
            __syncthreads();
            {   // u-build: i = og
                float v0[3] = {0.f, 0.f, 0.f};
                float v1[3] = {0.f, 0.f, 0.f};
                float v2[3] = {0.f, 0.f, 0.f};
                #pragma unroll
                for (int a = 0; a < 3; a++) {
                    if (((sl - a) & 1) == 0) {
                        int delta = (sl - a) / 2;     // -1, 0, or 1
                        int tlg = (2 * tg + delta + 16) & 15;
                        int w = delta + 1;            // 0..2
                        int jj = w * 16 + og;
                        v0[a] = __ldcg(&g_actA[(tlg * 16 + og) * 192 + n_g]);
                        v1[a] = sm[oC + (0 * 64 + jj) * 16 + n];
                        v2[a] = sm[oC + (1 * 64 + jj) * 16 + n];
                    }
                }
                float u[3];
                build_u(sm + oCK, v0, v1, v2, u);
                #pragma unroll
                for (int k = 0; k < 3; k++)
                    sm[oU + (og * 3 + k) * 16 + n] = u[k];
            }
            __syncthreads();
            if (og == 0) {                            // apply: CO = 1
                float a0 = 0.f;
                #pragma unroll
                for (int i = 0; i < 16; i++)
                    #pragma unroll
                    for (int k = 0; k < 3; k++)
                        a0 += sm[oH + i * 3 + k] * sm[oU + (i * 3 + k) * 16 + n];
                out[n_g * TT + (4 * tg + sl)] = a0;
            }
        }
    }
}

// ---------------- launch ---------------------------------------------------------
extern "C" void kernel_launch(void* const* d_in, const int* in_sizes, int n_in,
                              void* d_out, int out_size)
{
    const float* X    = (const float*)d_in[0];
    const float* Sg   = (const float*)d_in[1];
    const float* s    = (const float*)d_in[2];
    const float* h_e1 = (const float*)d_in[3];
    const float* h_e2 = (const float*)d_in[4];
    const float* h_d1 = (const float*)d_in[5];
    const float* h_d2 = (const float*)d_in[6];
    float* out = (float*)d_out;

    mega<<<NB, 256>>>(X, Sg, s, h_e1, h_e2, h_d1, h_d2, out);
}

// round 12
// speedup vs baseline: 1.4252x; 1.4252x over previous
#include <cuda_runtime.h>
#include <cstdint>

// GTConvAE — fused persistent kernel, R12 = R8 + cp.async-staged combines.
// Kronecker identity: S^k x[tau] = sum_{a,b<3} c_k[a][b] * Sg^b x[(tau-a) mod t].
// Layer = two GEMMs (G1=Sg@act, G2=Sg2@act) + 9-term combine with folded filters.
// Encoder fuses maxpool+relu; decoder exploits zero-stuffed upsampling.
// Combines now stream G rows through smem via a double-buffered cp.async group
// pipeline (16-row groups ping-ponged through Bs0/Bs1) instead of per-thread
// scalar __ldcg chains.

#define NN  192
#define TT  32
#define NB  128
#define KS  196

// ---------------- scratch --------------------------------------------------------
__device__ float g_Sg2 [NN * NN];
__device__ float g_G1  [256 * NN];
__device__ float g_G2  [256 * NN];
__device__ float g_actA[256 * NN];
__device__ float g_actB[256 * NN];
__device__ unsigned g_cnt = 0;
__device__ unsigned g_gen = 0;

// ---------------- grid barrier (R8 version) --------------------------------------
__device__ __forceinline__ void grid_barrier()
{
    __syncthreads();
    if (threadIdx.x == 0) {
        unsigned gen;
        asm volatile("ld.relaxed.gpu.u32 %0, [%1];"
                     : "=r"(gen) : "l"(&g_gen) : "memory");
        unsigned prev;
        asm volatile("atom.release.gpu.add.u32 %0, [%1], %2;"
                     : "=r"(prev) : "l"(&g_cnt), "r"(1u) : "memory");
        if (prev == NB - 1) {
            asm volatile("st.relaxed.gpu.u32 [%0], %1;"
                         :: "l"(&g_cnt), "r"(0u) : "memory");
            asm volatile("st.release.gpu.u32 [%0], %1;"
                         :: "l"(&g_gen), "r"(gen + 1u) : "memory");
        } else {
            unsigned cur;
            do {
                __nanosleep(16);
                asm volatile("ld.acquire.gpu.u32 %0, [%1];"
                             : "=r"(cur) : "l"(&g_gen) : "memory");
            } while (cur == gen);
        }
    }
    __syncthreads();
}

// ---------------- cp.async helpers ----------------------------------------------
__device__ __forceinline__ void cp16(float* dst, const float* src, bool cg)
{
    uint32_t d = (uint32_t)__cvta_generic_to_shared(dst);
    if (cg)
        asm volatile("cp.async.cg.shared.global [%0], [%1], 16;" :: "r"(d), "l"(src));
    else
        asm volatile("cp.async.ca.shared.global [%0], [%1], 16;" :: "r"(d), "l"(src));
}
__device__ __forceinline__ void cp_wait_all()
{
    asm volatile("cp.async.wait_all;" ::: "memory");
}
__device__ __forceinline__ void cp_commit()
{
    asm volatile("cp.async.commit_group;" ::: "memory");
}
template <int N>
__device__ __forceinline__ void cp_waitg()
{
    asm volatile("cp.async.wait_group %0;" :: "n"(N) : "memory");
}

// ---------------- tile loaders (128 threads) -------------------------------------
__device__ __forceinline__ void loadA24(const float* __restrict__ A, int m0,
                                        bool cg, float* As)
{
    #pragma unroll
    for (int r = 0; r < 9; r++) {
        int op = threadIdx.x + 128 * r;          // 0..1151
        int ml = op / 48, kq = op - ml * 48;
        cp16(&As[ml * KS + 4 * kq], &A[(m0 + ml) * NN + 4 * kq], cg);
    }
}
__device__ __forceinline__ void loadB16(const float* __restrict__ Bg, int j0,
                                        float* Bsb)
{
    #pragma unroll
    for (int r = 0; r < 6; r++) {
        int op = threadIdx.x + 128 * r;          // 0..767
        int jl = op / 48, kq = op - jl * 48;
        cp16(&Bsb[jl * KS + 4 * kq], &Bg[(j0 + jl) * NN + 4 * kq], true);
    }
}
// 16 contiguous act rows (192 floats) -> buf at natural stride 192
__device__ __forceinline__ void stage16(float* buf, const float* __restrict__ src)
{
    #pragma unroll
    for (int r = 0; r < 6; r++) {
        int op = threadIdx.x + 128 * r;          // 0..767
        int i = op / 48, c = op - i * 48;
        cp16(&buf[i * 192 + 4 * c], &src[i * 192 + 4 * c], true);
    }
}

// ---------------- compute one 24m x 16j tile (128 threads) -----------------------
template <bool CROW>
__device__ __forceinline__ void tile_compute(const float* __restrict__ As,
                                             const float* __restrict__ Bsb,
                                             float* __restrict__ C, int m0, int j0)
{
    const int tid = threadIdx.x;
    const int tx = tid & 15, ty = tid >> 4;      // j col, m base (0..7)
    float acc0 = 0.f, acc1 = 0.f, acc2 = 0.f;
    const float* bp  = Bsb + tx * KS;
    const float* ap0 = As + ty * KS;
    const float* ap1 = ap0 + 8 * KS;
    const float* ap2 = ap0 + 16 * KS;
    #pragma unroll 8
    for (int k = 0; k < NN; k += 4) {
        float4 b  = *(const float4*)(bp + k);
        float4 a0 = *(const float4*)(ap0 + k);
        float4 a1 = *(const float4*)(ap1 + k);
        float4 a2 = *(const float4*)(ap2 + k);
        acc0 += a0.x * b.x; acc0 += a0.y * b.y; acc0 += a0.z * b.z; acc0 += a0.w * b.w;
        acc1 += a1.x * b.x; acc1 += a1.y * b.y; acc1 += a1.z * b.z; acc1 += a1.w * b.w;
        acc2 += a2.x * b.x; acc2 += a2.y * b.y; acc2 += a2.z * b.z; acc2 += a2.w * b.w;
    }
    const int j = j0 + tx;
    if (CROW) {
        C[(m0 + ty     ) * NN + j] = acc0;
        C[(m0 + ty +  8) * NN + j] = acc1;
        C[(m0 + ty + 16) * NN + j] = acc2;
    } else {
        C[j * NN + m0 + ty     ] = acc0;
        C[j * NN + m0 + ty +  8] = acc1;
        C[j * NN + m0 + ty + 16] = acc2;
    }
}

// ---------------- big GEMM stage: 2 j-tiles, double-buffered B -------------------
template <bool LOADA>
__device__ void big_stage(const float* __restrict__ A, bool acg,
                          const float* __restrict__ Bact,
                          float* __restrict__ C, int m0, int j0,
                          float* As, float* Bs0, float* Bs1)
{
    if (LOADA) loadA24(A, m0, acg, As);
    loadB16(Bact, j0, Bs0);
    cp_wait_all(); __syncthreads();
    loadB16(Bact, j0 + 16, Bs1);
    tile_compute<false>(As, Bs0, C, m0, j0);
    cp_wait_all(); __syncthreads();
    tile_compute<false>(As, Bs1, C, m0, j0 + 16);
}

// ---------------- S0 tile: B from column-slices (Sg or X) ------------------------
template <int BMODE, bool CROW>
__device__ void s0_tile(const float* __restrict__ A, const float* __restrict__ Bg,
                        int j0, float* __restrict__ C, int m0,
                        float* As, float* Bs0)
{
    loadA24(A, m0, false, As);
    const int tid = threadIdx.x;
    #pragma unroll
    for (int r = 0; r < 24; r++) {
        int idx = tid + 128 * r;                 // 0..3071
        int jl = idx & 15, kk = idx >> 4;
        Bs0[jl * KS + kk] = (BMODE == 1) ? Bg[kk * NN + j0 + jl]
                                         : Bg[kk * TT + j0 + jl];
    }
    cp_wait_all(); __syncthreads();
    tile_compute<CROW>(As, Bs0, C, m0, j0);
}

// ---------------- folded filters -------------------------------------------------
__device__ __forceinline__ float fold_H(const float* __restrict__ h3,
                                        const float sv[4], int a, int b)
{
    float c0 = (a == 0 && b == 0) ? 1.f : 0.f;
    float c1 = (a < 2 && b < 2) ? sv[a * 2 + b] : 0.f;
    float c2 = 0.f;
    #pragma unroll
    for (int a1 = 0; a1 < 2; a1++)
        #pragma unroll
        for (int b1 = 0; b1 < 2; b1++) {
            int a2 = a - a1, b2 = b - b1;
            if (a2 >= 0 && a2 < 2 && b2 >= 0 && b2 < 2)
                c2 += sv[a1 * 2 + b1] * sv[a2 * 2 + b2];
        }
    return h3[0] * c0 + h3[1] * c1 + h3[2] * c2;
}

__device__ __forceinline__ void build_Hs(float* Hs, const float* __restrict__ h,
                                         const float sv[4], int CI, int OT, int ob)
{
    for (int idx = threadIdx.x; idx < CI * 9 * OT; idx += 128) {
        int oo = idx % OT;
        int tmp = idx / OT;
        int b = tmp % 3, a = (tmp / 3) % 3, i = tmp / 9;
        Hs[idx] = fold_H(&h[((ob + oo) * CI + i) * 3], sv, a, b);
    }
}

// ---------------- staged combine: e2 (CI=16, CO=32, OT=2, pool+relu) -------------
__device__ void combine_e2_staged(const float* __restrict__ h_e2,
                                  const float* __restrict__ sp,
                                  int tp, int ob, float* Hs, float* B0, float* B1)
{
    const int tid = threadIdx.x;
    const float sv[4] = { sp[0], sp[1], sp[2], sp[3] };
    build_Hs(Hs, h_e2, sv, 16, 2, ob);
    float* bufs[2] = { B0, B1 };

    auto gsrc = [&](int g) -> const float* {
        int tt = g / 3, mat = g - tt * 3;
        int sr = (2 * tp - 2 + tt + 16) & 15;
        const float* base = (mat == 0) ? g_actA : (mat == 1) ? g_G1 : g_G2;
        return base + (sr * 16) * NN;
    };

    stage16(bufs[0], gsrc(0)); cp_commit();
    float2 acc0[2] = { {0.f,0.f}, {0.f,0.f} };
    float2 acc1[2] = { {0.f,0.f}, {0.f,0.f} };
    const int n2 = 2 * (tid & 127);

    for (int g = 0; g < 12; g++) {
        if (g < 11) { stage16(bufs[(g + 1) & 1], gsrc(g + 1)); cp_commit(); cp_waitg<1>(); }
        else cp_waitg<0>();
        __syncthreads();
        if (tid < 96) {
            const float* B = bufs[g & 1];
            int tt = g / 3, mat = g - tt * 3;
            #pragma unroll
            for (int i = 0; i < 16; i++) {
                float2 v = *(const float2*)&B[i * 192 + n2];
                if (tt <= 2) {
                    int a = 2 - tt;
                    #pragma unroll
                    for (int o = 0; o < 2; o++) {
                        float hh = Hs[(i * 3 + a) * 6 + mat * 2 + o];
                        acc0[o].x += hh * v.x; acc0[o].y += hh * v.y;
                    }
                }
                if (tt >= 1) {
                    int a = 3 - tt;
                    #pragma unroll
                    for (int o = 0; o < 2; o++) {
                        float hh = Hs[(i * 3 + a) * 6 + mat * 2 + o];
                        acc1[o].x += hh * v.x; acc1[o].y += hh * v.y;
                    }
                }
            }
        }
        __syncthreads();
    }
    if (tid < 96) {
        #pragma unroll
        for (int o = 0; o < 2; o++) {
            float2 r;
            r.x = fmaxf(fmaxf(acc0[o].x, acc1[o].x), 0.f);
            r.y = fmaxf(fmaxf(acc0[o].y, acc1[o].y), 0.f);
            *(float2*)&g_actB[(tp * 32 + ob + o) * NN + n2] = r;
        }
    }
}

// ---------------- staged combine: d1 (CI=32, CO=16, OT=2, relu) ------------------
__device__ void combine_d1_staged(const float* __restrict__ h_d1,
                                  const float* __restrict__ sp,
                                  int tau, int ob, float* Hs, float* B0, float* B1)
{
    const int tid = threadIdx.x;
    const float sv[4] = { sp[0], sp[1], sp[2], sp[3] };
    build_Hs(Hs, h_d1, sv, 32, 2, ob);
    float* bufs[2] = { B0, B1 };
    const int ng = (tau & 1) ? 6 : 12;

    auto gparams = [&](int g, int& a, int& tl, int& ih, int& mat) {
        int tli = g / 6; ih = (g / 3) & 1; mat = g % 3;
        if (tau & 1) { a = 1; tl = (tau - 1) >> 1; }
        else         { a = tli ? 2 : 0; tl = ((tau >> 1) - tli) & 7; }
    };
    auto gsrc = [&](int g) -> const float* {
        int a, tl, ih, mat; gparams(g, a, tl, ih, mat);
        const float* base = (mat == 0) ? g_actB : (mat == 1) ? g_G1 : g_G2;
        return base + (tl * 32 + ih * 16) * NN;
    };

    stage16(bufs[0], gsrc(0)); cp_commit();
    float2 acc[2] = { {0.f,0.f}, {0.f,0.f} };
    const int n2 = 2 * (tid & 127);

    for (int g = 0; g < ng; g++) {
        if (g < ng - 1) { stage16(bufs[(g + 1) & 1], gsrc(g + 1)); cp_commit(); cp_waitg<1>(); }
        else cp_waitg<0>();
        __syncthreads();
        if (tid < 96) {
            const float* B = bufs[g & 1];
            int a, tl, ih, mat; gparams(g, a, tl, ih, mat);
            #pragma unroll
            for (int il = 0; il < 16; il++) {
                int i = ih * 16 + il;
                float2 v = *(const float2*)&B[il * 192 + n2];
                #pragma unroll
                for (int o = 0; o < 2; o++) {
                    float hh = Hs[(i * 3 + a) * 6 + mat * 2 + o];
                    acc[o].x += hh * v.x; acc[o].y += hh * v.y;
                }
            }
        }
        __syncthreads();
    }
    if (tid < 96) {
        #pragma unroll
        for (int o = 0; o < 2; o++) {
            float2 r;
            r.x = fmaxf(acc[o].x, 0.f);
            r.y = fmaxf(acc[o].y, 0.f);
            *(float2*)&g_actA[(tau * 16 + ob + o) * NN + n2] = r;
        }
    }
}

// ---------------- staged combine: final d2 (CI=16, CO=1) -------------------------
__device__ void combine_d2_staged(const float* __restrict__ h_d2,
                                  const float* __restrict__ sp,
                                  int tau, float* Hs, float* B0, float* B1,
                                  float* __restrict__ out)
{
    const int tid = threadIdx.x;
    const float sv[4] = { sp[0], sp[1], sp[2], sp[3] };
    build_Hs(Hs, h_d2, sv, 16, 1, 0);
    float* bufs[2] = { B0, B1 };
    const int ng = (tau & 1) ? 3 : 6;

    auto gparams = [&](int g, int& a, int& tl, int& mat) {
        int tli = g / 3; mat = g % 3;
        if (tau & 1) { a = 1; tl = (tau - 1) >> 1; }
        else         { a = tli ? 2 : 0; tl = ((tau >> 1) - tli) & 15; }
    };
    auto gsrc = [&](int g) -> const float* {
        int a, tl, mat; gparams(g, a, tl, mat);
        const float* base = (mat == 0) ? g_actA : (mat == 1) ? g_G1 : g_G2;
        return base + (tl * 16) * NN;
    };

    stage16(bufs[0], gsrc(0)); cp_commit();
    float2 acc = { 0.f, 0.f };
    const int n2 = 2 * (tid & 127);

    for (int g = 0; g < ng; g++) {
        if (g < ng - 1) { stage16(bufs[(g + 1) & 1], gsrc(g + 1)); cp_commit(); cp_waitg<1>(); }
        else cp_waitg<0>();
        __syncthreads();
        if (tid < 96) {
            const float* B = bufs[g & 1];
            int a, tl, mat; gparams(g, a, tl, mat);
            #pragma unroll
            for (int i = 0; i < 16; i++) {
                float2 v = *(const float2*)&B[i * 192 + n2];
                float hh = Hs[(i * 3 + a) * 3 + mat];
                acc.x += hh * v.x; acc.y += hh * v.y;
            }
        }
        __syncthreads();
    }
    if (tid < 96) {
        out[(n2    ) * TT + tau] = acc.x;
        out[(n2 + 1) * TT + tau] = acc.y;
    }
}

// ---------------- persistent mega-kernel ----------------------------------------
__global__ __launch_bounds__(128, 1) void mega(
    const float* __restrict__ X,    const float* __restrict__ Sg,
    const float* __restrict__ s,    const float* __restrict__ h_e1,
    const float* __restrict__ h_e2, const float* __restrict__ h_d1,
    const float* __restrict__ h_d2, float* __restrict__ out)
{
    __shared__ float As[24 * KS];    // 18.8 KB — persistent A band for S3/S5/S7
    __shared__ float Bs0[16 * KS];   // 12.5 KB — GEMM B buf / combine ping
    __shared__ float Bs1[16 * KS];   // 12.5 KB — GEMM B buf / combine pong
    __shared__ float Hs[576];
    __shared__ float G2s[96];

    const int bid = blockIdx.x;
    const int tid = threadIdx.x;

    const int mat = bid >> 6;                 // 0: Sg, 1: Sg2
    const int sub = bid & 63;
    const int gm0 = (sub >> 3) * 24;
    const int gj0 = (sub & 7) * 32;

    // ======== S0: Sg2 (96 tiles) + P = Sg@X (16 tiles) ========
    if (bid < 96) {
        int mb = bid / 12, jt = bid % 12;
        s0_tile<1, true>(Sg, Sg, jt * 16, g_Sg2, mb * 24, As, Bs0);
    } else if (bid < 112) {
        int b2 = bid - 96;
        int mb = b2 >> 1, jt = b2 & 1;
        s0_tile<2, false>(Sg, X, jt * 16, g_G1, mb * 24, As, Bs0);
    }
    grid_barrier();

    // ======== S1': e1 combine with fused mini-GEMM for G2 ========
    {
        const int tp = bid & 15, nb = bid >> 4;
        const int n0 = nb * 24;
        loadA24(Sg, n0, false, As);
        #pragma unroll
        for (int r = 0; r < 2; r++) {
            int op = tid + 128 * r;
            if (op < 192) {
                int ttl = op / 48, kq = op - ttl * 48;
                int src = (2 * tp - 2 + ttl + TT) & (TT - 1);
                cp16(&Bs0[ttl * KS + 4 * kq], &g_G1[src * NN + 4 * kq], true);
            }
        }
        const float sv[4] = { s[0], s[1], s[2], s[3] };
        for (int idx = tid; idx < 144; idx += 128) {   // CI=1, OT=16
            int o = idx & 15, ab = idx >> 4;
            Hs[idx] = fold_H(&h_e1[o * 3], sv, ab / 3, ab % 3);
        }
        cp_wait_all(); __syncthreads();
        if (tid < 96) {                       // mini-GEMM: 24 n x 4 src
            int nl = tid % 24, st = tid / 24;
            float acc = 0.f;
            const float* ap = As + nl * KS;
            const float* bp = Bs0 + st * KS;
            #pragma unroll 12
            for (int k = 0; k < NN; k += 4) {
                float4 a = *(const float4*)(ap + k);
                float4 b = *(const float4*)(bp + k);
                acc += a.x * b.x; acc += a.y * b.y; acc += a.z * b.z; acc += a.w * b.w;
            }
            G2s[st * 24 + nl] = acc;
        }
        __syncthreads();
        if (tid < 96) {
            int nl = tid % 24, og = tid / 24;
            int n = n0 + nl;
            float acc0[4] = {0.f, 0.f, 0.f, 0.f};
            float acc1[4] = {0.f, 0.f, 0.f, 0.f};
            #pragma unroll
            for (int ttl = 0; ttl < 4; ttl++) {
                int src = (2 * tp - 2 + ttl + TT) & (TT - 1);
                float v0 = X[n * TT + src];
                float v1 = Bs0[ttl * KS + n];
                float v2 = G2s[ttl * 24 + nl];
                if (ttl <= 2) {
                    int a = 2 - ttl;
                    #pragma unroll
                    for (int oo = 0; oo < 4; oo++) {
                        int o = og * 4 + oo;
                        acc0[oo] += Hs[(a * 3 + 0) * 16 + o] * v0
                                  + Hs[(a * 3 + 1) * 16 + o] * v1
                                  + Hs[(a * 3 + 2) * 16 + o] * v2;
                    }
                }
                if (ttl >= 1) {
                    int a = 3 - ttl;
                    #pragma unroll
                    for (int oo = 0; oo < 4; oo++) {
                        int o = og * 4 + oo;
                        acc1[oo] += Hs[(a * 3 + 0) * 16 + o] * v0
                                  + Hs[(a * 3 + 1) * 16 + o] * v1
                                  + Hs[(a * 3 + 2) * 16 + o] * v2;
                    }
                }
            }
            #pragma unroll
            for (int oo = 0; oo < 4; oo++) {
                int o = og * 4 + oo;
                g_actA[(tp * 16 + o) * NN + n] = fmaxf(fmaxf(acc0[oo], acc1[oo]), 0.f);
            }
        }
    }
    grid_barrier();

    // ======== S3: e2 GEMMs ========
    if (mat == 0)
        big_stage<true>(Sg, false, g_actA, g_G1, gm0, gj0, As, Bs0, Bs1);
    else
        big_stage<true>(g_Sg2, true, g_actA, g_G2, gm0, gj0, As, Bs0, Bs1);
    grid_barrier();

    // ======== S4: combine e2 -> actB (staged) ========
    {
        int tp = bid & 7, obg = bid >> 3;      // 16 groups of OT=2
        combine_e2_staged(h_e2, s, tp, obg * 2, Hs, Bs0, Bs1);
    }
    grid_barrier();

    // ======== S5: d1 GEMMs (A resident) ========
    big_stage<false>(nullptr, false, g_actB, mat ? g_G2 : g_G1, gm0, gj0, As, Bs0, Bs1);
    grid_barrier();

    // ======== S6: combine d1 -> actA (staged) ========
    {
        int tau = bid & 15, obg = bid >> 4;    // 8 groups of OT=2
        combine_d1_staged(h_d1, s, tau, obg * 2, Hs, Bs0, Bs1);
    }
    grid_barrier();

    // ======== S7: d2 GEMMs (A resident) ========
    big_stage<false>(nullptr, false, g_actA, mat ? g_G2 : g_G1, gm0, gj0, As, Bs0, Bs1);
    grid_barrier();

    // ======== S8: final combine d2 -> out (staged) ========
    if (bid < 32)
        combine_d2_staged(h_d2, s, bid, Hs, Bs0, Bs1, out);
}

// ---------------- launch ---------------------------------------------------------
extern "C" void kernel_launch(void* const* d_in, const int* in_sizes, int n_in,
                              void* d_out, int out_size)
{
    const float* X    = (const float*)d_in[0];
    const float* Sg   = (const float*)d_in[1];
    const float* s    = (const float*)d_in[2];
    const float* h_e1 = (const float*)d_in[3];
    const float* h_e2 = (const float*)d_in[4];
    const float* h_d1 = (const float*)d_in[5];
    const float* h_d2 = (const float*)d_in[6];
    float* out = (float*)d_out;

    mega<<<NB, 128>>>(X, Sg, s, h_e1, h_e2, h_d1, h_d2, out);
}

// round 13
// speedup vs baseline: 1.5899x; 1.1156x over previous
#include <cuda_runtime.h>
#include <cstdint>

// GTConvAE — fused persistent kernel, R13 = R8 + split arrive/wait barriers with
// overlapped prep (filter-table builds + next-stage A-band cp.async prefetch).
// Kronecker identity: S^k x[tau] = sum_{a,b<3} c_k[a][b] * Sg^b x[(tau-a) mod t].
// Layer = two GEMMs (G1=Sg@act, G2=Sg2@act) + 9-term combine with folded filters.
// Encoder fuses maxpool+relu; decoder exploits zero-stuffed upsampling.

#define NN  192
#define TT  32
#define NB  128
#define KS  196

// ---------------- scratch --------------------------------------------------------
__device__ float g_Sg2 [NN * NN];
__device__ float g_G1  [256 * NN];
__device__ float g_G2  [256 * NN];
__device__ float g_actA[256 * NN];
__device__ float g_actB[256 * NN];
__device__ unsigned g_cnt = 0;
__device__ unsigned g_gen = 0;

// ---------------- split grid barrier ---------------------------------------------
// tid0 only. arrive() returns the generation to wait for; wait(target) spins.
__device__ __forceinline__ unsigned bar_arrive()
{
    unsigned gen;
    asm volatile("ld.relaxed.gpu.u32 %0, [%1];"
                 : "=r"(gen) : "l"(&g_gen) : "memory");
    unsigned prev;
    asm volatile("atom.release.gpu.add.u32 %0, [%1], %2;"
                 : "=r"(prev) : "l"(&g_cnt), "r"(1u) : "memory");
    if (prev == NB - 1) {
        asm volatile("st.relaxed.gpu.u32 [%0], %1;"
                     :: "l"(&g_cnt), "r"(0u) : "memory");
        asm volatile("st.release.gpu.u32 [%0], %1;"
                     :: "l"(&g_gen), "r"(gen + 1u) : "memory");
    }
    return gen + 1;
}
__device__ __forceinline__ void bar_wait(unsigned target)
{
    unsigned cur;
    do {
        asm volatile("ld.acquire.gpu.u32 %0, [%1];"
                     : "=r"(cur) : "l"(&g_gen) : "memory");
    } while ((int)(cur - target) < 0);
}

// ---------------- cp.async helpers ----------------------------------------------
__device__ __forceinline__ void cp16(float* dst, const float* src, bool cg)
{
    uint32_t d = (uint32_t)__cvta_generic_to_shared(dst);
    if (cg)
        asm volatile("cp.async.cg.shared.global [%0], [%1], 16;" :: "r"(d), "l"(src));
    else
        asm volatile("cp.async.ca.shared.global [%0], [%1], 16;" :: "r"(d), "l"(src));
}
__device__ __forceinline__ void cp_wait_all()
{
    asm volatile("cp.async.wait_all;" ::: "memory");
}

// ---------------- tile loaders (128 threads) -------------------------------------
__device__ __forceinline__ void loadA24(const float* __restrict__ A, int m0,
                                        bool cg, float* As)
{
    #pragma unroll
    for (int r = 0; r < 9; r++) {
        int op = threadIdx.x + 128 * r;          // 0..1151
        int ml = op / 48, kq = op - ml * 48;
        cp16(&As[ml * KS + 4 * kq], &A[(m0 + ml) * NN + 4 * kq], cg);
    }
}
__device__ __forceinline__ void loadB16(const float* __restrict__ Bg, int j0,
                                        float* Bsb)
{
    #pragma unroll
    for (int r = 0; r < 6; r++) {
        int op = threadIdx.x + 128 * r;          // 0..767
        int jl = op / 48, kq = op - jl * 48;
        cp16(&Bsb[jl * KS + 4 * kq], &Bg[(j0 + jl) * NN + 4 * kq], true);
    }
}

// ---------------- compute one 24m x 16j tile (128 threads) -----------------------
template <bool CROW>
__device__ __forceinline__ void tile_compute(const float* __restrict__ As,
                                             const float* __restrict__ Bsb,
                                             float* __restrict__ C, int m0, int j0)
{
    const int tid = threadIdx.x;
    const int tx = tid & 15, ty = tid >> 4;
    float acc0 = 0.f, acc1 = 0.f, acc2 = 0.f;
    const float* bp  = Bsb + tx * KS;
    const float* ap0 = As + ty * KS;
    const float* ap1 = ap0 + 8 * KS;
    const float* ap2 = ap0 + 16 * KS;
    #pragma unroll 8
    for (int k = 0; k < NN; k += 4) {
        float4 b  = *(const float4*)(bp + k);
        float4 a0 = *(const float4*)(ap0 + k);
        float4 a1 = *(const float4*)(ap1 + k);
        float4 a2 = *(const float4*)(ap2 + k);
        acc0 += a0.x * b.x; acc0 += a0.y * b.y; acc0 += a0.z * b.z; acc0 += a0.w * b.w;
        acc1 += a1.x * b.x; acc1 += a1.y * b.y; acc1 += a1.z * b.z; acc1 += a1.w * b.w;
        acc2 += a2.x * b.x; acc2 += a2.y * b.y; acc2 += a2.z * b.z; acc2 += a2.w * b.w;
    }
    const int j = j0 + tx;
    if (CROW) {
        C[(m0 + ty     ) * NN + j] = acc0;
        C[(m0 + ty +  8) * NN + j] = acc1;
        C[(m0 + ty + 16) * NN + j] = acc2;
    } else {
        C[j * NN + m0 + ty     ] = acc0;
        C[j * NN + m0 + ty +  8] = acc1;
        C[j * NN + m0 + ty + 16] = acc2;
    }
}

// ---------------- big GEMM stage: 2 j-tiles, double-buffered B -------------------
template <bool LOADA>
__device__ void big_stage(const float* __restrict__ A, bool acg,
                          const float* __restrict__ Bact,
                          float* __restrict__ C, int m0, int j0,
                          float* As, float* Bs0, float* Bs1)
{
    if (LOADA) loadA24(A, m0, acg, As);
    loadB16(Bact, j0, Bs0);
    cp_wait_all(); __syncthreads();
    loadB16(Bact, j0 + 16, Bs1);
    tile_compute<false>(As, Bs0, C, m0, j0);
    cp_wait_all(); __syncthreads();
    tile_compute<false>(As, Bs1, C, m0, j0 + 16);
}

// ---------------- S0 tile: B from column-slices (Sg or X) ------------------------
template <int BMODE, bool CROW>
__device__ void s0_tile(const float* __restrict__ A, const float* __restrict__ Bg,
                        int j0, float* __restrict__ C, int m0,
                        float* As, float* Bs0)
{
    loadA24(A, m0, false, As);
    const int tid = threadIdx.x;
    #pragma unroll
    for (int r = 0; r < 24; r++) {
        int idx = tid + 128 * r;                 // 0..3071
        int jl = idx & 15, kk = idx >> 4;
        Bs0[jl * KS + kk] = (BMODE == 1) ? Bg[kk * NN + j0 + jl]
                                         : Bg[kk * TT + j0 + jl];
    }
    cp_wait_all(); __syncthreads();
    tile_compute<CROW>(As, Bs0, C, m0, j0);
}

// ---------------- folded filters -------------------------------------------------
__device__ __forceinline__ float fold_H(const float* __restrict__ h3,
                                        const float sv[4], int a, int b)
{
    float c0 = (a == 0 && b == 0) ? 1.f : 0.f;
    float c1 = (a < 2 && b < 2) ? sv[a * 2 + b] : 0.f;
    float c2 = 0.f;
    #pragma unroll
    for (int a1 = 0; a1 < 2; a1++)
        #pragma unroll
        for (int b1 = 0; b1 < 2; b1++) {
            int a2 = a - a1, b2 = b - b1;
            if (a2 >= 0 && a2 < 2 && b2 >= 0 && b2 < 2)
                c2 += sv[a1 * 2 + b1] * sv[a2 * 2 + b2];
        }
    return h3[0] * c0 + h3[1] * c1 + h3[2] * c2;
}

__device__ __forceinline__ void build_Hs(float* Hs, const float* __restrict__ h,
                                         const float sv[4], int CI, int OT, int ob)
{
    for (int idx = threadIdx.x; idx < CI * 9 * OT; idx += 128) {
        int oo = idx % OT;
        int tmp = idx / OT;
        int b = tmp % 3, a = (tmp / 3) % 3, i = tmp / 9;
        Hs[idx] = fold_H(&h[((ob + oo) * CI + i) * 3], sv, a, b);
    }
}

// ---------------- encoder combine body (Hs prebuilt): float2, 96 threads ---------
template <int CI, int CO, int OT>
__device__ void combine_enc_body(const float* __restrict__ G0,
                                 const float* __restrict__ G1,
                                 const float* __restrict__ G2,
                                 float* __restrict__ out, int t, int tp, int ob,
                                 const float* Hs)
{
    const int tid = threadIdx.x;
    if (tid < 96) {
        const int n2 = 2 * tid;
        float2 acc0[OT], acc1[OT];
        #pragma unroll
        for (int o = 0; o < OT; o++) {
            acc0[o] = make_float2(0.f, 0.f); acc1[o] = make_float2(0.f, 0.f);
        }
        #pragma unroll
        for (int tt = 0; tt < 4; tt++) {
            int src = (2 * tp - 2 + tt + t) & (t - 1);
            #pragma unroll
            for (int i = 0; i < CI; i++) {
                float2 v0 = __ldcg((const float2*)&G0[(src * CI + i) * NN + n2]);
                float2 v1 = __ldcg((const float2*)&G1[(src * CI + i) * NN + n2]);
                float2 v2 = __ldcg((const float2*)&G2[(src * CI + i) * NN + n2]);
                if (tt <= 2) {
                    const float* Hp = &Hs[(i * 3 + (2 - tt)) * 3 * OT];
                    #pragma unroll
                    for (int o = 0; o < OT; o++) {
                        float h0 = Hp[o], h1 = Hp[OT + o], h2 = Hp[2 * OT + o];
                        acc0[o].x += h0 * v0.x + h1 * v1.x + h2 * v2.x;
                        acc0[o].y += h0 * v0.y + h1 * v1.y + h2 * v2.y;
                    }
                }
                if (tt >= 1) {
                    const float* Hp = &Hs[(i * 3 + (3 - tt)) * 3 * OT];
                    #pragma unroll
                    for (int o = 0; o < OT; o++) {
                        float h0 = Hp[o], h1 = Hp[OT + o], h2 = Hp[2 * OT + o];
                        acc1[o].x += h0 * v0.x + h1 * v1.x + h2 * v2.x;
                        acc1[o].y += h0 * v0.y + h1 * v1.y + h2 * v2.y;
                    }
                }
            }
        }
        #pragma unroll
        for (int o = 0; o < OT; o++) {
            float2 r;
            r.x = fmaxf(fmaxf(acc0[o].x, acc1[o].x), 0.f);
            r.y = fmaxf(fmaxf(acc0[o].y, acc1[o].y), 0.f);
            *(float2*)&out[(tp * CO + ob + o) * NN + n2] = r;
        }
    }
}

// ---------------- decoder combine body (Hs prebuilt) -----------------------------
template <int CI, int CO, int OT>
__device__ void combine_dec_body(const float* __restrict__ G0,
                                 const float* __restrict__ G1,
                                 const float* __restrict__ G2,
                                 float* __restrict__ out, int t, int tau, int ob,
                                 const float* Hs)
{
    const int tid = threadIdx.x;
    if (tid < 96) {
        const int n2 = 2 * tid;
        float2 acc[OT];
        #pragma unroll
        for (int o = 0; o < OT; o++) acc[o] = make_float2(0.f, 0.f);
        #pragma unroll
        for (int a = 0; a < 3; a++) {
            int src = tau - a; if (src < 0) src += t;
            if (src & 1) continue;             // zero-stuffed upsample
            int tl = src >> 1;
            #pragma unroll 16
            for (int i = 0; i < CI; i++) {
                float2 v0 = __ldcg((const float2*)&G0[(tl * CI + i) * NN + n2]);
                float2 v1 = __ldcg((const float2*)&G1[(tl * CI + i) * NN + n2]);
                float2 v2 = __ldcg((const float2*)&G2[(tl * CI + i) * NN + n2]);
                const float* Hp = &Hs[(i * 3 + a) * 3 * OT];
                #pragma unroll
                for (int o = 0; o < OT; o++) {
                    float h0 = Hp[o], h1 = Hp[OT + o], h2 = Hp[2 * OT + o];
                    acc[o].x += h0 * v0.x + h1 * v1.x + h2 * v2.x;
                    acc[o].y += h0 * v0.y + h1 * v1.y + h2 * v2.y;
                }
            }
        }
        #pragma unroll
        for (int o = 0; o < OT; o++) {
            float2 r;
            r.x = fmaxf(acc[o].x, 0.f);
            r.y = fmaxf(acc[o].y, 0.f);
            *(float2*)&out[(tau * CO + ob + o) * NN + n2] = r;
        }
    }
}

// ---------------- persistent mega-kernel ----------------------------------------
__global__ __launch_bounds__(128, 1) void mega(
    const float* __restrict__ X,    const float* __restrict__ Sg,
    const float* __restrict__ s,    const float* __restrict__ h_e1,
    const float* __restrict__ h_e2, const float* __restrict__ h_d1,
    const float* __restrict__ h_d2, float* __restrict__ out)
{
    __shared__ float As[24 * KS];    // persistent A band
    __shared__ float Bs0[16 * KS];
    __shared__ float Bs1[16 * KS];
    __shared__ float Hs[576];
    __shared__ float G2s[96];

    const int bid = blockIdx.x;
    const int tid = threadIdx.x;

    const int mat = bid >> 6;                 // 0: Sg, 1: Sg2
    const int sub = bid & 63;
    const int gm0 = (sub >> 3) * 24;
    const int gj0 = (sub & 7) * 32;

    const float sv[4] = { s[0], s[1], s[2], s[3] };
    unsigned bg = 0;

    // ======== S0: Sg2 (96 tiles) + P = Sg@X (16 tiles) ========
    if (bid < 96) {
        int mb = bid / 12, jt = bid % 12;
        s0_tile<1, true>(Sg, Sg, jt * 16, g_Sg2, mb * 24, As, Bs0);
    } else if (bid < 112) {
        int b2 = bid - 96;
        int mb = b2 >> 1, jt = b2 & 1;
        s0_tile<2, false>(Sg, X, jt * 16, g_G1, mb * 24, As, Bs0);
    }
    // --- barrier 1 with overlapped prep: e1 Hs + S1' mini-GEMM A band (Sg rows) --
    __syncthreads();
    if (tid == 0) bg = bar_arrive();
    {
        const int nb = bid >> 4;
        loadA24(Sg, nb * 24, false, As);      // S1' A (input — barrier-independent)
        for (int idx = tid; idx < 144; idx += 128) {   // CI=1, OT=16 table
            int o = idx & 15, ab = idx >> 4;
            Hs[idx] = fold_H(&h_e1[o * 3], sv, ab / 3, ab % 3);
        }
    }
    if (tid == 0) bar_wait(bg);
    __syncthreads();

    // ======== S1': e1 combine with fused mini-GEMM for G2 ========
    {
        const int tp = bid & 15, nb = bid >> 4;
        const int n0 = nb * 24;
        #pragma unroll
        for (int r = 0; r < 2; r++) {         // P rows for 4 source taus
            int op = tid + 128 * r;
            if (op < 192) {
                int ttl = op / 48, kq = op - ttl * 48;
                int src = (2 * tp - 2 + ttl + TT) & (TT - 1);
                cp16(&Bs0[ttl * KS + 4 * kq], &g_G1[src * NN + 4 * kq], true);
            }
        }
        cp_wait_all(); __syncthreads();
        if (tid < 96) {                       // mini-GEMM: 24 n x 4 src
            int nl = tid % 24, st = tid / 24;
            float acc = 0.f;
            const float* ap = As + nl * KS;
            const float* bp = Bs0 + st * KS;
            #pragma unroll 12
            for (int k = 0; k < NN; k += 4) {
                float4 a = *(const float4*)(ap + k);
                float4 b = *(const float4*)(bp + k);
                acc += a.x * b.x; acc += a.y * b.y; acc += a.z * b.z; acc += a.w * b.w;
            }
            G2s[st * 24 + nl] = acc;
        }
        __syncthreads();
        if (tid < 96) {                       // combine: 24 n x 4 o-groups of 4
            int nl = tid % 24, og = tid / 24;
            int n = n0 + nl;
            float acc0[4] = {0.f, 0.f, 0.f, 0.f};
            float acc1[4] = {0.f, 0.f, 0.f, 0.f};
            #pragma unroll
            for (int ttl = 0; ttl < 4; ttl++) {
                int src = (2 * tp - 2 + ttl + TT) & (TT - 1);
                float v0 = X[n * TT + src];
                float v1 = Bs0[ttl * KS + n];
                float v2 = G2s[ttl * 24 + nl];
                if (ttl <= 2) {
                    int a = 2 - ttl;
                    #pragma unroll
                    for (int oo = 0; oo < 4; oo++) {
                        int o = og * 4 + oo;
                        acc0[oo] += Hs[(a * 3 + 0) * 16 + o] * v0
                                  + Hs[(a * 3 + 1) * 16 + o] * v1
                                  + Hs[(a * 3 + 2) * 16 + o] * v2;
                    }
                }
                if (ttl >= 1) {
                    int a = 3 - ttl;
                    #pragma unroll
                    for (int oo = 0; oo < 4; oo++) {
                        int o = og * 4 + oo;
                        acc1[oo] += Hs[(a * 3 + 0) * 16 + o] * v0
                                  + Hs[(a * 3 + 1) * 16 + o] * v1
                                  + Hs[(a * 3 + 2) * 16 + o] * v2;
                    }
                }
            }
            #pragma unroll
            for (int oo = 0; oo < 4; oo++) {
                int o = og * 4 + oo;
                g_actA[(tp * 16 + o) * NN + n] = fmaxf(fmaxf(acc0[oo], acc1[oo]), 0.f);
            }
        }
    }
    // --- barrier 2 with overlapped prep: S3 A band (Sg/Sg2, stable since bar 1) --
    __syncthreads();
    if (tid == 0) bg = bar_arrive();
    loadA24(mat ? g_Sg2 : Sg, gm0, mat != 0, As);
    if (tid == 0) bar_wait(bg);
    __syncthreads();

    // ======== S3: e2 GEMMs (A band prefetched) ========
    big_stage<false>(nullptr, false, g_actA, mat ? g_G2 : g_G1, gm0, gj0, As, Bs0, Bs1);
    // --- barrier 3 with overlapped prep: e2 combine Hs ---
    __syncthreads();
    if (tid == 0) bg = bar_arrive();
    build_Hs(Hs, h_e2, sv, 16, 2, (bid >> 3) * 2);
    if (tid == 0) bar_wait(bg);
    __syncthreads();

    // ======== S4: combine e2 -> actB ========
    combine_enc_body<16, 32, 2>(g_actA, g_G1, g_G2, g_actB, 16,
                                bid & 7, (bid >> 3) * 2, Hs);
    // --- barrier 4 (A band for S5 already resident) ---
    __syncthreads();
    if (tid == 0) { bg = bar_arrive(); bar_wait(bg); }
    __syncthreads();

    // ======== S5: d1 GEMMs (A resident) ========
    big_stage<false>(nullptr, false, g_actB, mat ? g_G2 : g_G1, gm0, gj0, As, Bs0, Bs1);
    // --- barrier 5 with overlapped prep: d1 combine Hs ---
    __syncthreads();
    if (tid == 0) bg = bar_arrive();
    build_Hs(Hs, h_d1, sv, 32, 2, (bid >> 4) * 2);
    if (tid == 0) bar_wait(bg);
    __syncthreads();

    // ======== S6: combine d1 -> actA ========
    combine_dec_body<32, 16, 2>(g_actB, g_G1, g_G2, g_actA, 16,
                                bid & 15, (bid >> 4) * 2, Hs);
    // --- barrier 6 ---
    __syncthreads();
    if (tid == 0) { bg = bar_arrive(); bar_wait(bg); }
    __syncthreads();

    // ======== S7: d2 GEMMs (A resident) ========
    big_stage<false>(nullptr, false, g_actA, mat ? g_G2 : g_G1, gm0, gj0, As, Bs0, Bs1);
    // --- barrier 7 with overlapped prep: d2 Hs (blocks < 32) ---
    __syncthreads();
    if (tid == 0) bg = bar_arrive();
    if (bid < 32) {
        for (int idx = tid; idx < 144; idx += 128) {   // CI=16, OT=1
            int b = idx % 3, a = (idx / 3) % 3, i = idx / 9;
            Hs[idx] = fold_H(&h_d2[i * 3], sv, a, b);
        }
    }
    if (tid == 0) bar_wait(bg);
    __syncthreads();

    // ======== S8: final combine d2 -> out (N, T) ========
    if (bid < 32) {
        const int tau = bid;
        if (tid < 96) {
            const int n2 = 2 * tid;
            float2 acc = make_float2(0.f, 0.f);
            #pragma unroll
            for (int a = 0; a < 3; a++) {
                int src = tau - a; if (src < 0) src += TT;
                if (src & 1) continue;
                int tl = src >> 1;
                #pragma unroll
                for (int i = 0; i < 16; i++) {
                    float2 v0 = __ldcg((const float2*)&g_actA[(tl * 16 + i) * NN + n2]);
                    float2 v1 = __ldcg((const float2*)&g_G1[(tl * 16 + i) * NN + n2]);
                    float2 v2 = __ldcg((const float2*)&g_G2[(tl * 16 + i) * NN + n2]);
                    float h0 = Hs[(i * 3 + a) * 3 + 0];
                    float h1 = Hs[(i * 3 + a) * 3 + 1];
                    float h2 = Hs[(i * 3 + a) * 3 + 2];
                    acc.x += h0 * v0.x + h1 * v1.x + h2 * v2.x;
                    acc.y += h0 * v0.y + h1 * v1.y + h2 * v2.y;
                }
            }
            out[(n2    ) * TT + tau] = acc.x;
            out[(n2 + 1) * TT + tau] = acc.y;
        }
    }
}

// ---------------- launch ---------------------------------------------------------
extern "C" void kernel_launch(void* const* d_in, const int* in_sizes, int n_in,
                              void* d_out, int out_size)
{
    const float* X    = (const float*)d_in[0];
    const float* Sg   = (const float*)d_in[1];
    const float* s    = (const float*)d_in[2];
    const float* h_e1 = (const float*)d_in[3];
    const float* h_e2 = (const float*)d_in[4];
    const float* h_d1 = (const float*)d_in[5];
    const float* h_d2 = (const float*)d_in[6];
    float* out = (float*)d_out;

    mega<<<NB, 128>>>(X, Sg, s, h_e1, h_e2, h_d1, h_d2, out);
}